// round 12
// baseline (speedup 1.0000x reference)
#include <cuda_runtime.h>
#include <cuda_bf16.h>
#include <math.h>

// Problem constants
#define BB 2
#define SS 2048
#define DD 1024
#define HH 16
#define DHH 64
#define D3 3072
#define MTOT 4096   // B*S

// ---------------- scratch (device globals; no allocation allowed) ----------------
__device__ float sb_xn[MTOT * DD];
__device__ float sb_qkv[MTOT * D3];
__device__ float sb_u[MTOT * DD];
__device__ float sb_ams[MTOT * DD];
__device__ float sb_o[MTOT * DD];
__device__ float sb_on[MTOT * DD];
__device__ float sb_x12[MTOT * 2 * DD];
__device__ float sb_h[MTOT * DD];

__device__ __forceinline__ float silu_f(float v) {
    return v / (1.0f + expf(-v));
}

// ---------------- RMSNorm ----------------
__global__ __launch_bounds__(256) void rmsnorm_kernel(const float* __restrict__ x,
                                                      const float* __restrict__ g,
                                                      float* __restrict__ out) {
    const int row = blockIdx.x;
    const float* xr = x + (size_t)row * DD;
    float s = 0.0f;
    #pragma unroll
    for (int i = threadIdx.x; i < DD; i += 256) {
        float v = xr[i];
        s += v * v;
    }
    __shared__ float red[8];
    #pragma unroll
    for (int o = 16; o > 0; o >>= 1) s += __shfl_down_sync(0xffffffffu, s, o);
    if ((threadIdx.x & 31) == 0) red[threadIdx.x >> 5] = s;
    __syncthreads();
    if (threadIdx.x < 32) {
        s = (threadIdx.x < 8) ? red[threadIdx.x] : 0.0f;
        #pragma unroll
        for (int o = 4; o > 0; o >>= 1) s += __shfl_down_sync(0xffffffffu, s, o);
        if (threadIdx.x == 0) red[0] = s;
    }
    __syncthreads();
    const float r = rsqrtf(red[0] * (1.0f / DD) + 1e-8f);
    float* orow = out + (size_t)row * DD;
    #pragma unroll
    for (int i = threadIdx.x; i < DD; i += 256) {
        orow[i] = g[i] * (xr[i] * r);
    }
}

// ---------------- SGEMM: C[M,N] = A[M,K] @ B[N,K]^T (+ epilogue) ----------------
// EPI: 0 = none, 1 = silu, 2 = add Res
template <int EPI>
__global__ __launch_bounds__(256) void sgemm(const float* __restrict__ A,
                                             const float* __restrict__ Bm,
                                             float* __restrict__ C,
                                             const float* __restrict__ Res,
                                             int M, int N, int K) {
    __shared__ __align__(16) float As[16][132];
    __shared__ __align__(16) float Bs[16][132];
    const int tid = threadIdx.x;
    const int tx = tid & 15;
    const int ty = tid >> 4;
    const int m0 = blockIdx.y * 128;
    const int n0 = blockIdx.x * 128;

    float acc[8][8];
    #pragma unroll
    for (int i = 0; i < 8; i++)
        #pragma unroll
        for (int j = 0; j < 8; j++) acc[i][j] = 0.0f;

    const float* Aptr = A + (size_t)m0 * K;
    const float* Bptr = Bm + (size_t)n0 * K;

    for (int k0 = 0; k0 < K; k0 += 16) {
        #pragma unroll
        for (int t = 0; t < 2; t++) {
            int f = tid + t * 256;
            int r = f >> 2;
            int cv = (f & 3) << 2;
            float4 va = *(const float4*)(Aptr + (size_t)r * K + k0 + cv);
            As[cv + 0][r] = va.x; As[cv + 1][r] = va.y;
            As[cv + 2][r] = va.z; As[cv + 3][r] = va.w;
            float4 vb = *(const float4*)(Bptr + (size_t)r * K + k0 + cv);
            Bs[cv + 0][r] = vb.x; Bs[cv + 1][r] = vb.y;
            Bs[cv + 2][r] = vb.z; Bs[cv + 3][r] = vb.w;
        }
        __syncthreads();
        #pragma unroll
        for (int kk = 0; kk < 16; kk++) {
            float a[8], b[8];
            *(float4*)&a[0] = *(const float4*)&As[kk][ty * 4];
            *(float4*)&a[4] = *(const float4*)&As[kk][64 + ty * 4];
            *(float4*)&b[0] = *(const float4*)&Bs[kk][tx * 4];
            *(float4*)&b[4] = *(const float4*)&Bs[kk][64 + tx * 4];
            #pragma unroll
            for (int i = 0; i < 8; i++)
                #pragma unroll
                for (int j = 0; j < 8; j++)
                    acc[i][j] += a[i] * b[j];
        }
        __syncthreads();
    }

    #pragma unroll
    for (int ih = 0; ih < 2; ih++)
        #pragma unroll
        for (int i = 0; i < 4; i++) {
            const int r = m0 + ih * 64 + ty * 4 + i;
            #pragma unroll
            for (int jh = 0; jh < 2; jh++) {
                const int c = n0 + jh * 64 + tx * 4;
                float4 v;
                v.x = acc[ih * 4 + i][jh * 4 + 0];
                v.y = acc[ih * 4 + i][jh * 4 + 1];
                v.z = acc[ih * 4 + i][jh * 4 + 2];
                v.w = acc[ih * 4 + i][jh * 4 + 3];
                if (EPI == 1) {
                    v.x = silu_f(v.x); v.y = silu_f(v.y);
                    v.z = silu_f(v.z); v.w = silu_f(v.w);
                }
                if (EPI == 2) {
                    float4 rv = *(const float4*)(Res + (size_t)r * N + c);
                    v.x += rv.x; v.y += rv.y; v.z += rv.z; v.w += rv.w;
                }
                *(float4*)(C + (size_t)r * N + c) = v;
            }
        }
}

// ---------------- Attention (SiLU "softmax", causal, fused *u) ----------------
// grid (S/64, H, B), 256 threads. smem: Q,K,V,P tiles 64x64 (stride 65).
#define ASTRIDE 65
#define ATTN_SMEM (4 * 64 * ASTRIDE * 4)

__global__ __launch_bounds__(256) void attn_kernel(const float* __restrict__ qkv,
                                                   const float* __restrict__ pbias,
                                                   const float* __restrict__ u,
                                                   float* __restrict__ ams) {
    extern __shared__ float sm[];
    float* Qs = sm;
    float* Ks = sm + 64 * ASTRIDE;
    float* Vs = sm + 2 * 64 * ASTRIDE;
    float* Ps = sm + 3 * 64 * ASTRIDE;

    const int tid = threadIdx.x;
    const int tx = tid & 15;
    const int ty = tid >> 4;
    const int q0 = blockIdx.x * 64;
    const int h = blockIdx.y;
    const int b = blockIdx.z;
    const size_t base = (size_t)b * SS * D3;

    // load Q tile (64 x 64)
    for (int t = tid; t < 64 * 16; t += 256) {
        int r = t >> 4;
        int cv = (t & 15) << 2;
        float4 v = *(const float4*)(qkv + base + (size_t)(q0 + r) * D3 + h * DHH + cv);
        Qs[r * ASTRIDE + cv + 0] = v.x;
        Qs[r * ASTRIDE + cv + 1] = v.y;
        Qs[r * ASTRIDE + cv + 2] = v.z;
        Qs[r * ASTRIDE + cv + 3] = v.w;
    }

    float acc[4][4];
    #pragma unroll
    for (int i = 0; i < 4; i++)
        #pragma unroll
        for (int j = 0; j < 4; j++) acc[i][j] = 0.0f;

    const float scale = 0.125f;  // 1/sqrt(64)

    for (int j0 = 0; j0 <= q0; j0 += 64) {
        __syncthreads();  // prior-iter readers of Ks/Vs done; Q store visible (first iter)
        for (int t = tid; t < 64 * 16; t += 256) {
            int r = t >> 4;
            int cv = (t & 15) << 2;
            float4 vk = *(const float4*)(qkv + base + (size_t)(j0 + r) * D3 + DD + h * DHH + cv);
            Ks[r * ASTRIDE + cv + 0] = vk.x;
            Ks[r * ASTRIDE + cv + 1] = vk.y;
            Ks[r * ASTRIDE + cv + 2] = vk.z;
            Ks[r * ASTRIDE + cv + 3] = vk.w;
            float4 vv = *(const float4*)(qkv + base + (size_t)(j0 + r) * D3 + 2 * DD + h * DHH + cv);
            Vs[r * ASTRIDE + cv + 0] = vv.x;
            Vs[r * ASTRIDE + cv + 1] = vv.y;
            Vs[r * ASTRIDE + cv + 2] = vv.z;
            Vs[r * ASTRIDE + cv + 3] = vv.w;
        }
        __syncthreads();

        // S = Q @ K^T (4x4 per thread)
        float s[4][4];
        #pragma unroll
        for (int i = 0; i < 4; i++)
            #pragma unroll
            for (int j = 0; j < 4; j++) s[i][j] = 0.0f;

        #pragma unroll 8
        for (int d = 0; d < 64; d++) {
            float qa[4], kb[4];
            #pragma unroll
            for (int i = 0; i < 4; i++) qa[i] = Qs[(ty * 4 + i) * ASTRIDE + d];
            #pragma unroll
            for (int j = 0; j < 4; j++) kb[j] = Ks[(tx * 4 + j) * ASTRIDE + d];
            #pragma unroll
            for (int i = 0; i < 4; i++)
                #pragma unroll
                for (int j = 0; j < 4; j++)
                    s[i][j] += qa[i] * kb[j];
        }

        // bias + causal + silu -> Ps
        const float* pb = pbias + ((size_t)h * SS + q0) * SS + j0;
        #pragma unroll
        for (int i = 0; i < 4; i++) {
            const int q = ty * 4 + i;
            float4 bv = *(const float4*)(pb + (size_t)q * SS + tx * 4);
            float bb[4] = {bv.x, bv.y, bv.z, bv.w};
            #pragma unroll
            for (int j = 0; j < 4; j++) {
                const int kpos = j0 + tx * 4 + j;
                const float sc = s[i][j] * scale + bb[j];
                const float p = (kpos <= q0 + q) ? silu_f(sc) : 0.0f;
                Ps[q * ASTRIDE + tx * 4 + j] = p;
            }
        }
        __syncthreads();

        // acc += P @ V
        #pragma unroll 8
        for (int k = 0; k < 64; k++) {
            float pv[4], vv[4];
            #pragma unroll
            for (int i = 0; i < 4; i++) pv[i] = Ps[(ty * 4 + i) * ASTRIDE + k];
            #pragma unroll
            for (int j = 0; j < 4; j++) vv[j] = Vs[k * ASTRIDE + tx * 4 + j];
            #pragma unroll
            for (int i = 0; i < 4; i++)
                #pragma unroll
                for (int j = 0; j < 4; j++)
                    acc[i][j] += pv[i] * vv[j];
        }
    }

    // epilogue: ams = attn * u
    const size_t orow = ((size_t)b * SS + q0) * DD + h * DHH;
    #pragma unroll
    for (int i = 0; i < 4; i++) {
        const size_t off = orow + (size_t)(ty * 4 + i) * DD + tx * 4;
        float4 uv = *(const float4*)(u + off);
        float4 ov;
        ov.x = acc[i][0] * uv.x;
        ov.y = acc[i][1] * uv.y;
        ov.z = acc[i][2] * uv.z;
        ov.w = acc[i][3] * uv.w;
        *(float4*)(ams + off) = ov;
    }
}

// ---------------- SwiGLU elementwise ----------------
__global__ __launch_bounds__(256) void swiglu_kernel(const float* __restrict__ x12,
                                                     float* __restrict__ hout) {
    const int idx = blockIdx.x * 256 + threadIdx.x;  // 0 .. MTOT*DD
    const int m = idx >> 10;
    const int n = idx & 1023;
    const float a = x12[(size_t)m * 2048 + n];
    const float c = x12[(size_t)m * 2048 + 1024 + n];
    hout[idx] = silu_f(a) * c;
}

// ---------------- launch ----------------
extern "C" void kernel_launch(void* const* d_in, const int* in_sizes, int n_in,
                              void* d_out, int out_size) {
    const float* x      = (const float*)d_in[0];
    const float* pbias  = (const float*)d_in[1];
    // d_in[2] = mask: unused (causality handled analytically; silu(-1e9) == -0)
    const float* w_qkv  = (const float*)d_in[3];
    const float* w_u    = (const float*)d_in[4];
    const float* g_ams  = (const float*)d_in[5];
    const float* w0     = (const float*)d_in[6];
    const float* w1     = (const float*)d_in[7];
    const float* w3     = (const float*)d_in[8];
    const float* g_mffn = (const float*)d_in[9];
    float* out = (float*)d_out;

    float *xn, *qkvb, *ub, *amsb, *ob, *onb, *x12b, *hb;
    cudaGetSymbolAddress((void**)&xn,   sb_xn);
    cudaGetSymbolAddress((void**)&qkvb, sb_qkv);
    cudaGetSymbolAddress((void**)&ub,   sb_u);
    cudaGetSymbolAddress((void**)&amsb, sb_ams);
    cudaGetSymbolAddress((void**)&ob,   sb_o);
    cudaGetSymbolAddress((void**)&onb,  sb_on);
    cudaGetSymbolAddress((void**)&x12b, sb_x12);
    cudaGetSymbolAddress((void**)&hb,   sb_h);

    cudaFuncSetAttribute(attn_kernel, cudaFuncAttributeMaxDynamicSharedMemorySize, ATTN_SMEM);

    // 1) xn = rmsnorm(x, g_ams)
    rmsnorm_kernel<<<MTOT, 256>>>(x, g_ams, xn);
    // 2) qkv = xn @ w_qkv^T
    sgemm<0><<<dim3(D3 / 128, MTOT / 128), 256>>>(xn, w_qkv, qkvb, nullptr, MTOT, D3, DD);
    // 3) u = silu(xn @ w_u^T)
    sgemm<1><<<dim3(DD / 128, MTOT / 128), 256>>>(xn, w_u, ub, nullptr, MTOT, DD, DD);
    // 4) ams = attn(q,k,v, bias, causal) * u
    attn_kernel<<<dim3(SS / 64, HH, BB), 256, ATTN_SMEM>>>(qkvb, pbias, ub, amsb);
    // 5) o = ams @ w0^T + x
    sgemm<2><<<dim3(DD / 128, MTOT / 128), 256>>>(amsb, w0, ob, x, MTOT, DD, DD);
    // 6) on = rmsnorm(o, g_mffn)
    rmsnorm_kernel<<<MTOT, 256>>>(ob, g_mffn, onb);
    // 7) x12 = on @ w1^T
    sgemm<0><<<dim3(2 * DD / 128, MTOT / 128), 256>>>(onb, w1, x12b, nullptr, MTOT, 2 * DD, DD);
    // 8) hidden = silu(x1) * x2
    swiglu_kernel<<<(MTOT * DD) / 256, 256>>>(x12b, hb);
    // 9) out = hidden @ w3^T + o
    sgemm<2><<<dim3(DD / 128, MTOT / 128), 256>>>(hb, w3, out, ob, MTOT, DD, DD);
}

// round 13
// speedup vs baseline: 1.0038x; 1.0038x over previous
#include <cuda_runtime.h>
#include <cuda_bf16.h>
#include <math.h>

// Problem constants
#define BB 2
#define SS 2048
#define DD 1024
#define HH 16
#define DHH 64
#define D3 3072
#define MTOT 4096   // B*S

// ---------------- scratch (device globals; no allocation allowed) ----------------
__device__ float sb_xn[MTOT * DD];
__device__ float sb_qkv[MTOT * D3];
__device__ float sb_u[MTOT * DD];
__device__ float sb_ams[MTOT * DD];
__device__ float sb_o[MTOT * DD];
__device__ float sb_on[MTOT * DD];
__device__ float sb_x12[MTOT * 2 * DD];
__device__ float sb_h[MTOT * DD];

__device__ __forceinline__ float silu_f(float v) {
    return v / (1.0f + expf(-v));
}

// ---------------- RMSNorm ----------------
__global__ __launch_bounds__(256) void rmsnorm_kernel(const float* __restrict__ x,
                                                      const float* __restrict__ g,
                                                      float* __restrict__ out) {
    const int row = blockIdx.x;
    const float* xr = x + (size_t)row * DD;
    float s = 0.0f;
    #pragma unroll
    for (int i = threadIdx.x; i < DD; i += 256) {
        float v = xr[i];
        s += v * v;
    }
    __shared__ float red[8];
    #pragma unroll
    for (int o = 16; o > 0; o >>= 1) s += __shfl_down_sync(0xffffffffu, s, o);
    if ((threadIdx.x & 31) == 0) red[threadIdx.x >> 5] = s;
    __syncthreads();
    if (threadIdx.x < 32) {
        s = (threadIdx.x < 8) ? red[threadIdx.x] : 0.0f;
        #pragma unroll
        for (int o = 4; o > 0; o >>= 1) s += __shfl_down_sync(0xffffffffu, s, o);
        if (threadIdx.x == 0) red[0] = s;
    }
    __syncthreads();
    const float r = rsqrtf(red[0] * (1.0f / DD) + 1e-8f);
    float* orow = out + (size_t)row * DD;
    #pragma unroll
    for (int i = threadIdx.x; i < DD; i += 256) {
        orow[i] = g[i] * (xr[i] * r);
    }
}

// ---------------- SGEMM: C[M,N] = A[M,K] @ B[N,K]^T (+ epilogue) ----------------
// EPI: 0 = none, 1 = silu, 2 = add Res
template <int EPI>
__global__ __launch_bounds__(256) void sgemm(const float* __restrict__ A,
                                             const float* __restrict__ Bm,
                                             float* __restrict__ C,
                                             const float* __restrict__ Res,
                                             int M, int N, int K) {
    __shared__ __align__(16) float As[16][132];
    __shared__ __align__(16) float Bs[16][132];
    const int tid = threadIdx.x;
    const int tx = tid & 15;
    const int ty = tid >> 4;
    const int m0 = blockIdx.y * 128;
    const int n0 = blockIdx.x * 128;

    float acc[8][8];
    #pragma unroll
    for (int i = 0; i < 8; i++)
        #pragma unroll
        for (int j = 0; j < 8; j++) acc[i][j] = 0.0f;

    const float* Aptr = A + (size_t)m0 * K;
    const float* Bptr = Bm + (size_t)n0 * K;

    for (int k0 = 0; k0 < K; k0 += 16) {
        #pragma unroll
        for (int t = 0; t < 2; t++) {
            int f = tid + t * 256;
            int r = f >> 2;
            int cv = (f & 3) << 2;
            float4 va = *(const float4*)(Aptr + (size_t)r * K + k0 + cv);
            As[cv + 0][r] = va.x; As[cv + 1][r] = va.y;
            As[cv + 2][r] = va.z; As[cv + 3][r] = va.w;
            float4 vb = *(const float4*)(Bptr + (size_t)r * K + k0 + cv);
            Bs[cv + 0][r] = vb.x; Bs[cv + 1][r] = vb.y;
            Bs[cv + 2][r] = vb.z; Bs[cv + 3][r] = vb.w;
        }
        __syncthreads();
        #pragma unroll
        for (int kk = 0; kk < 16; kk++) {
            float a[8], b[8];
            *(float4*)&a[0] = *(const float4*)&As[kk][ty * 4];
            *(float4*)&a[4] = *(const float4*)&As[kk][64 + ty * 4];
            *(float4*)&b[0] = *(const float4*)&Bs[kk][tx * 4];
            *(float4*)&b[4] = *(const float4*)&Bs[kk][64 + tx * 4];
            #pragma unroll
            for (int i = 0; i < 8; i++)
                #pragma unroll
                for (int j = 0; j < 8; j++)
                    acc[i][j] += a[i] * b[j];
        }
        __syncthreads();
    }

    #pragma unroll
    for (int ih = 0; ih < 2; ih++)
        #pragma unroll
        for (int i = 0; i < 4; i++) {
            const int r = m0 + ih * 64 + ty * 4 + i;
            #pragma unroll
            for (int jh = 0; jh < 2; jh++) {
                const int c = n0 + jh * 64 + tx * 4;
                float4 v;
                v.x = acc[ih * 4 + i][jh * 4 + 0];
                v.y = acc[ih * 4 + i][jh * 4 + 1];
                v.z = acc[ih * 4 + i][jh * 4 + 2];
                v.w = acc[ih * 4 + i][jh * 4 + 3];
                if (EPI == 1) {
                    v.x = silu_f(v.x); v.y = silu_f(v.y);
                    v.z = silu_f(v.z); v.w = silu_f(v.w);
                }
                if (EPI == 2) {
                    float4 rv = *(const float4*)(Res + (size_t)r * N + c);
                    v.x += rv.x; v.y += rv.y; v.z += rv.z; v.w += rv.w;
                }
                *(float4*)(C + (size_t)r * N + c) = v;
            }
        }
}

// ---------------- Attention (SiLU "softmax", causal, fused *u) ----------------
// grid (S/64, H, B), 256 threads. smem: Q,K,V,P tiles 64x64 (stride 65).
#define ASTRIDE 65
#define ATTN_SMEM (4 * 64 * ASTRIDE * 4)

__global__ __launch_bounds__(256) void attn_kernel(const float* __restrict__ qkv,
                                                   const float* __restrict__ pbias,
                                                   const float* __restrict__ u,
                                                   float* __restrict__ ams) {
    extern __shared__ float sm[];
    float* Qs = sm;
    float* Ks = sm + 64 * ASTRIDE;
    float* Vs = sm + 2 * 64 * ASTRIDE;
    float* Ps = sm + 3 * 64 * ASTRIDE;

    const int tid = threadIdx.x;
    const int tx = tid & 15;
    const int ty = tid >> 4;
    const int q0 = blockIdx.x * 64;
    const int h = blockIdx.y;
    const int b = blockIdx.z;
    const size_t base = (size_t)b * SS * D3;

    // load Q tile (64 x 64)
    for (int t = tid; t < 64 * 16; t += 256) {
        int r = t >> 4;
        int cv = (t & 15) << 2;
        float4 v = *(const float4*)(qkv + base + (size_t)(q0 + r) * D3 + h * DHH + cv);
        Qs[r * ASTRIDE + cv + 0] = v.x;
        Qs[r * ASTRIDE + cv + 1] = v.y;
        Qs[r * ASTRIDE + cv + 2] = v.z;
        Qs[r * ASTRIDE + cv + 3] = v.w;
    }

    float acc[4][4];
    #pragma unroll
    for (int i = 0; i < 4; i++)
        #pragma unroll
        for (int j = 0; j < 4; j++) acc[i][j] = 0.0f;

    const float scale = 0.125f;  // 1/sqrt(64)

    for (int j0 = 0; j0 <= q0; j0 += 64) {
        __syncthreads();  // prior-iter readers of Ks/Vs done; Q store visible (first iter)
        for (int t = tid; t < 64 * 16; t += 256) {
            int r = t >> 4;
            int cv = (t & 15) << 2;
            float4 vk = *(const float4*)(qkv + base + (size_t)(j0 + r) * D3 + DD + h * DHH + cv);
            Ks[r * ASTRIDE + cv + 0] = vk.x;
            Ks[r * ASTRIDE + cv + 1] = vk.y;
            Ks[r * ASTRIDE + cv + 2] = vk.z;
            Ks[r * ASTRIDE + cv + 3] = vk.w;
            float4 vv = *(const float4*)(qkv + base + (size_t)(j0 + r) * D3 + 2 * DD + h * DHH + cv);
            Vs[r * ASTRIDE + cv + 0] = vv.x;
            Vs[r * ASTRIDE + cv + 1] = vv.y;
            Vs[r * ASTRIDE + cv + 2] = vv.z;
            Vs[r * ASTRIDE + cv + 3] = vv.w;
        }
        __syncthreads();

        // S = Q @ K^T (4x4 per thread)
        float s[4][4];
        #pragma unroll
        for (int i = 0; i < 4; i++)
            #pragma unroll
            for (int j = 0; j < 4; j++) s[i][j] = 0.0f;

        #pragma unroll 8
        for (int d = 0; d < 64; d++) {
            float qa[4], kb[4];
            #pragma unroll
            for (int i = 0; i < 4; i++) qa[i] = Qs[(ty * 4 + i) * ASTRIDE + d];
            #pragma unroll
            for (int j = 0; j < 4; j++) kb[j] = Ks[(tx * 4 + j) * ASTRIDE + d];
            #pragma unroll
            for (int i = 0; i < 4; i++)
                #pragma unroll
                for (int j = 0; j < 4; j++)
                    s[i][j] += qa[i] * kb[j];
        }

        // bias + causal + silu -> Ps
        const float* pb = pbias + ((size_t)h * SS + q0) * SS + j0;
        #pragma unroll
        for (int i = 0; i < 4; i++) {
            const int q = ty * 4 + i;
            float4 bv = *(const float4*)(pb + (size_t)q * SS + tx * 4);
            float bb[4] = {bv.x, bv.y, bv.z, bv.w};
            #pragma unroll
            for (int j = 0; j < 4; j++) {
                const int kpos = j0 + tx * 4 + j;
                const float sc = s[i][j] * scale + bb[j];
                const float p = (kpos <= q0 + q) ? silu_f(sc) : 0.0f;
                Ps[q * ASTRIDE + tx * 4 + j] = p;
            }
        }
        __syncthreads();

        // acc += P @ V
        #pragma unroll 8
        for (int k = 0; k < 64; k++) {
            float pv[4], vv[4];
            #pragma unroll
            for (int i = 0; i < 4; i++) pv[i] = Ps[(ty * 4 + i) * ASTRIDE + k];
            #pragma unroll
            for (int j = 0; j < 4; j++) vv[j] = Vs[k * ASTRIDE + tx * 4 + j];
            #pragma unroll
            for (int i = 0; i < 4; i++)
                #pragma unroll
                for (int j = 0; j < 4; j++)
                    acc[i][j] += pv[i] * vv[j];
        }
    }

    // epilogue: ams = attn * u
    const size_t orow = ((size_t)b * SS + q0) * DD + h * DHH;
    #pragma unroll
    for (int i = 0; i < 4; i++) {
        const size_t off = orow + (size_t)(ty * 4 + i) * DD + tx * 4;
        float4 uv = *(const float4*)(u + off);
        float4 ov;
        ov.x = acc[i][0] * uv.x;
        ov.y = acc[i][1] * uv.y;
        ov.z = acc[i][2] * uv.z;
        ov.w = acc[i][3] * uv.w;
        *(float4*)(ams + off) = ov;
    }
}

// ---------------- SwiGLU elementwise ----------------
__global__ __launch_bounds__(256) void swiglu_kernel(const float* __restrict__ x12,
                                                     float* __restrict__ hout) {
    const int idx = blockIdx.x * 256 + threadIdx.x;  // 0 .. MTOT*DD
    const int m = idx >> 10;
    const int n = idx & 1023;
    const float a = x12[(size_t)m * 2048 + n];
    const float c = x12[(size_t)m * 2048 + 1024 + n];
    hout[idx] = silu_f(a) * c;
}

// ---------------- launch ----------------
extern "C" void kernel_launch(void* const* d_in, const int* in_sizes, int n_in,
                              void* d_out, int out_size) {
    const float* x      = (const float*)d_in[0];
    const float* pbias  = (const float*)d_in[1];
    // d_in[2] = mask: unused (causality handled analytically; silu(-1e9) == -0)
    const float* w_qkv  = (const float*)d_in[3];
    const float* w_u    = (const float*)d_in[4];
    const float* g_ams  = (const float*)d_in[5];
    const float* w0     = (const float*)d_in[6];
    const float* w1     = (const float*)d_in[7];
    const float* w3     = (const float*)d_in[8];
    const float* g_mffn = (const float*)d_in[9];
    float* out = (float*)d_out;

    float *xn, *qkvb, *ub, *amsb, *ob, *onb, *x12b, *hb;
    cudaGetSymbolAddress((void**)&xn,   sb_xn);
    cudaGetSymbolAddress((void**)&qkvb, sb_qkv);
    cudaGetSymbolAddress((void**)&ub,   sb_u);
    cudaGetSymbolAddress((void**)&amsb, sb_ams);
    cudaGetSymbolAddress((void**)&ob,   sb_o);
    cudaGetSymbolAddress((void**)&onb,  sb_on);
    cudaGetSymbolAddress((void**)&x12b, sb_x12);
    cudaGetSymbolAddress((void**)&hb,   sb_h);

    cudaFuncSetAttribute(attn_kernel, cudaFuncAttributeMaxDynamicSharedMemorySize, ATTN_SMEM);

    // 1) xn = rmsnorm(x, g_ams)
    rmsnorm_kernel<<<MTOT, 256>>>(x, g_ams, xn);
    // 2) qkv = xn @ w_qkv^T
    sgemm<0><<<dim3(D3 / 128, MTOT / 128), 256>>>(xn, w_qkv, qkvb, nullptr, MTOT, D3, DD);
    // 3) u = silu(xn @ w_u^T)
    sgemm<1><<<dim3(DD / 128, MTOT / 128), 256>>>(xn, w_u, ub, nullptr, MTOT, DD, DD);
    // 4) ams = attn(q,k,v, bias, causal) * u
    attn_kernel<<<dim3(SS / 64, HH, BB), 256, ATTN_SMEM>>>(qkvb, pbias, ub, amsb);
    // 5) o = ams @ w0^T + x
    sgemm<2><<<dim3(DD / 128, MTOT / 128), 256>>>(amsb, w0, ob, x, MTOT, DD, DD);
    // 6) on = rmsnorm(o, g_mffn)
    rmsnorm_kernel<<<MTOT, 256>>>(ob, g_mffn, onb);
    // 7) x12 = on @ w1^T
    sgemm<0><<<dim3(2 * DD / 128, MTOT / 128), 256>>>(onb, w1, x12b, nullptr, MTOT, 2 * DD, DD);
    // 8) hidden = silu(x1) * x2
    swiglu_kernel<<<(MTOT * DD) / 256, 256>>>(x12b, hb);
    // 9) out = hidden @ w3^T + o
    sgemm<2><<<dim3(DD / 128, MTOT / 128), 256>>>(hb, w3, out, ob, MTOT, DD, DD);
}